// round 1
// baseline (speedup 1.0000x reference)
#include <cuda_runtime.h>
#include <cuda_bf16.h>
#include <cuda_fp8.h>
#include <mma.h>

using namespace nvcuda;

// Fixed max capacities (problem: B=4,S=2048,D_IN=4096,D_OUT=4096)
#define M_MAX 8192
#define N_MAX 4096
#define K_MAX 4096

// Scratch (device globals: allocation-free rule)
__device__ __nv_bfloat16 g_xq[(size_t)M_MAX * K_MAX];   // 64 MB
__device__ __nv_bfloat16 g_wq[(size_t)N_MAX * K_MAX];   // 32 MB
__device__ unsigned int g_amax_bits;

__global__ void reset_kernel() { g_amax_bits = 0u; }

__global__ void amax_kernel(const float4* __restrict__ x, long n4) {
    float m = 0.f;
    long i = (long)blockIdx.x * blockDim.x + threadIdx.x;
    long stride = (long)gridDim.x * blockDim.x;
    for (; i < n4; i += stride) {
        float4 v = x[i];
        m = fmaxf(m, fmaxf(fmaxf(fabsf(v.x), fabsf(v.y)), fmaxf(fabsf(v.z), fabsf(v.w))));
    }
    #pragma unroll
    for (int o = 16; o; o >>= 1) m = fmaxf(m, __shfl_xor_sync(0xffffffffu, m, o));
    __shared__ float sm[32];
    int lane = threadIdx.x & 31, wid = threadIdx.x >> 5;
    if (lane == 0) sm[wid] = m;
    __syncthreads();
    if (wid == 0) {
        m = (lane < (int)(blockDim.x >> 5)) ? sm[lane] : 0.f;
        #pragma unroll
        for (int o = 16; o; o >>= 1) m = fmaxf(m, __shfl_xor_sync(0xffffffffu, m, o));
        if (lane == 0) atomicMax(&g_amax_bits, __float_as_uint(m));
    }
}

__device__ __forceinline__ float fp8_round(float v) {
    __nv_fp8_storage_t r = __nv_cvt_float_to_fp8(v, __NV_SATFINITE, __NV_E4M3);
    return __half2float(__nv_cvt_fp8_to_halfraw(r, __NV_E4M3));
}

// qinput = fp8_round(x / scale); stored as bf16 (exact for e4m3 values)
__global__ void quant_x_kernel(const float4* __restrict__ x, long n4) {
    float amax = __uint_as_float(g_amax_bits);
    float scale = fmaxf(amax, 1e-12f) / 448.f;
    long i = (long)blockIdx.x * blockDim.x + threadIdx.x;
    long stride = (long)gridDim.x * blockDim.x;
    uint2* dst = (uint2*)g_xq;
    for (; i < n4; i += stride) {
        float4 v = x[i];
        __nv_bfloat162 h0, h1;
        h0.x = __float2bfloat16(fp8_round(v.x / scale));
        h0.y = __float2bfloat16(fp8_round(v.y / scale));
        h1.x = __float2bfloat16(fp8_round(v.z / scale));
        h1.y = __float2bfloat16(fp8_round(v.w / scale));
        uint2 u;
        u.x = *(unsigned int*)&h0;
        u.y = *(unsigned int*)&h1;
        dst[i] = u;
    }
}

// qw = fp8_round(qweight); stored as bf16
__global__ void quant_w_kernel(const float4* __restrict__ w, long n4) {
    long i = (long)blockIdx.x * blockDim.x + threadIdx.x;
    long stride = (long)gridDim.x * blockDim.x;
    uint2* dst = (uint2*)g_wq;
    for (; i < n4; i += stride) {
        float4 v = w[i];
        __nv_bfloat162 h0, h1;
        h0.x = __float2bfloat16(fp8_round(v.x));
        h0.y = __float2bfloat16(fp8_round(v.y));
        h1.x = __float2bfloat16(fp8_round(v.z));
        h1.y = __float2bfloat16(fp8_round(v.w));
        uint2 u;
        u.x = *(unsigned int*)&h0;
        u.y = *(unsigned int*)&h1;
        dst[i] = u;
    }
}

// ---------------- GEMM: out[M,N] = s * (Xq @ Wq^T) + bias ----------------
// BM=128, BN=128, BK=32, 256 threads (8 warps as 2x4), WMMA bf16 m16n16k16,
// double-buffered smem tiles via cp.async.

#define BM 128
#define BN 128
#define BK 32
#define LDS 40                  // padded smem row stride (elements)
#define BUF_BYTES 20480         // (A:128*40 + B:128*40) * 2B per buffer

__global__ void __launch_bounds__(256, 2)
gemm_kernel(const float* __restrict__ bias, const float* __restrict__ wscale_p,
            float* __restrict__ out, int M, int N, int K) {
    __shared__ __align__(16) unsigned char smem_raw[2 * BUF_BYTES];

    const int bm = blockIdx.y * BM;
    const int bn = blockIdx.x * BN;
    const int tid = threadIdx.x;
    const int wid = tid >> 5;
    const int lane = tid & 31;
    const int warp_m = wid & 1;   // 0..1 -> 64 rows each
    const int warp_n = wid >> 1;  // 0..3 -> 32 cols each

    const __nv_bfloat16* Ag = g_xq + (size_t)bm * K;
    const __nv_bfloat16* Bg = g_wq + (size_t)bn * K;

    wmma::fragment<wmma::accumulator, 16, 16, 16, float> acc[4][2];
    #pragma unroll
    for (int i = 0; i < 4; i++)
        #pragma unroll
        for (int j = 0; j < 2; j++)
            wmma::fill_fragment(acc[i][j], 0.f);

    const int KT = K / BK;

    auto load_tile = [&](int buf, int kt) {
        int k0 = kt * BK;
        unsigned sA = (unsigned)__cvta_generic_to_shared(smem_raw + buf * BUF_BYTES);
        unsigned sB = sA + BM * LDS * 2;
        #pragma unroll
        for (int i = 0; i < 2; i++) {
            int id = tid + i * 256;          // 0..511
            int r = id >> 2;                  // row 0..127
            int c = id & 3;                   // 16B chunk 0..3
            unsigned off = (unsigned)(r * LDS + c * 8) * 2u;
            const __nv_bfloat16* srcA = Ag + (size_t)r * K + k0 + c * 8;
            const __nv_bfloat16* srcB = Bg + (size_t)r * K + k0 + c * 8;
            asm volatile("cp.async.cg.shared.global [%0], [%1], 16;\n" ::"r"(sA + off), "l"(srcA));
            asm volatile("cp.async.cg.shared.global [%0], [%1], 16;\n" ::"r"(sB + off), "l"(srcB));
        }
    };

    load_tile(0, 0);
    asm volatile("cp.async.commit_group;\n");

    for (int kt = 0; kt < KT; kt++) {
        int buf = kt & 1;
        if (kt + 1 < KT) load_tile(buf ^ 1, kt + 1);
        asm volatile("cp.async.commit_group;\n");
        asm volatile("cp.async.wait_group 1;\n");
        __syncthreads();

        const __nv_bfloat16* Ab = (const __nv_bfloat16*)(smem_raw + buf * BUF_BYTES);
        const __nv_bfloat16* Bb = Ab + BM * LDS;

        #pragma unroll
        for (int ks = 0; ks < 2; ks++) {
            wmma::fragment<wmma::matrix_a, 16, 16, 16, __nv_bfloat16, wmma::row_major> af[4];
            wmma::fragment<wmma::matrix_b, 16, 16, 16, __nv_bfloat16, wmma::col_major> bfr[2];
            #pragma unroll
            for (int i = 0; i < 4; i++)
                wmma::load_matrix_sync(af[i], Ab + (warp_m * 64 + i * 16) * LDS + ks * 16, LDS);
            #pragma unroll
            for (int j = 0; j < 2; j++)
                wmma::load_matrix_sync(bfr[j], Bb + (warp_n * 32 + j * 16) * LDS + ks * 16, LDS);
            #pragma unroll
            for (int i = 0; i < 4; i++)
                #pragma unroll
                for (int j = 0; j < 2; j++)
                    wmma::mma_sync(acc[i][j], af[i], bfr[j], acc[i][j]);
        }
        __syncthreads();
    }

    // Epilogue: out = acc * (sa*sw) + bias
    float sw = *wscale_p;
    float amax = __uint_as_float(g_amax_bits);
    float s = (fmaxf(amax, 1e-12f) / 448.f) * sw;

    float* scratch = (float*)smem_raw + wid * 256;   // 16x16 per warp (reuses A buf, compute is done)
    const int r = lane >> 1;
    const int ch = (lane & 1) * 8;

    #pragma unroll
    for (int j = 0; j < 2; j++) {
        int gn = bn + warp_n * 32 + j * 16 + ch;
        float4 bb0 = *(const float4*)(bias + gn);
        float4 bb1 = *(const float4*)(bias + gn + 4);
        #pragma unroll
        for (int i = 0; i < 4; i++) {
            wmma::store_matrix_sync(scratch, acc[i][j], 16, wmma::mem_row_major);
            __syncwarp();
            int gm = bm + warp_m * 64 + i * 16 + r;
            const float* src = scratch + r * 16 + ch;
            float4 v0 = *(const float4*)(src);
            float4 v1 = *(const float4*)(src + 4);
            v0.x = v0.x * s + bb0.x; v0.y = v0.y * s + bb0.y;
            v0.z = v0.z * s + bb0.z; v0.w = v0.w * s + bb0.w;
            v1.x = v1.x * s + bb1.x; v1.y = v1.y * s + bb1.y;
            v1.z = v1.z * s + bb1.z; v1.w = v1.w * s + bb1.w;
            float* dst = out + (size_t)gm * N + gn;
            *(float4*)(dst) = v0;
            *(float4*)(dst + 4) = v1;
            __syncwarp();
        }
    }
}

extern "C" void kernel_launch(void* const* d_in, const int* in_sizes, int n_in,
                              void* d_out, int out_size) {
    const float* x      = (const float*)d_in[0];
    const float* qw     = (const float*)d_in[1];
    const float* wscale = (const float*)d_in[2];
    const float* bias   = (const float*)d_in[3];
    float* out = (float*)d_out;

    const long xn = in_sizes[0];           // M*K
    const long wn = in_sizes[1];           // N*K
    const int  N  = in_sizes[3];           // D_OUT
    const int  K  = (int)(wn / N);
    const int  M  = (int)(xn / K);

    reset_kernel<<<1, 1>>>();
    amax_kernel<<<2048, 256>>>((const float4*)x, xn / 4);
    quant_x_kernel<<<8192, 256>>>((const float4*)x, xn / 4);
    quant_w_kernel<<<4096, 256>>>((const float4*)qw, wn / 4);

    dim3 grid(N / BN, M / BM);
    gemm_kernel<<<grid, 256>>>(bias, wscale, out, M, N, K);
}

// round 6
// speedup vs baseline: 1.2821x; 1.2821x over previous
#include <cuda_runtime.h>
#include <cuda_bf16.h>
#include <cuda_fp8.h>

// Problem shape: M=8192 (B*S), N=4096, K=4096
#define M_MAX 8192
#define NTOT  4096
#define KTOT  4096

#define BM 128
#define BN 128
#define BK 64
#define NST 4
#define TILE_BYTES 8192                  // 128 rows x 64 B
#define STG_BYTES (2 * TILE_BYTES)       // A + B per stage
#define SMEM_DYN (NST * STG_BYTES)       // 64 KB
#define KTILES (KTOT / BK)               // 64

// fp8 scratch, tiled: tile t = (rowtile * KTILES + ktile), 8 KB contiguous.
// Within a tile: row r (64B), 16B chunk c stored at r*64 + (c ^ ((r>>1)&3))*16.
__device__ __align__(128) unsigned char g_xq[(size_t)M_MAX * KTOT];  // 32 MB
__device__ __align__(128) unsigned char g_wq[(size_t)NTOT * KTOT];   // 16 MB
__device__ unsigned int g_amax_bits;

__global__ void reset_kernel() { g_amax_bits = 0u; }

__global__ void amax_kernel(const float4* __restrict__ x, long n4) {
    float m = 0.f;
    long i = (long)blockIdx.x * blockDim.x + threadIdx.x;
    long stride = (long)gridDim.x * blockDim.x;
    for (; i < n4; i += stride) {
        float4 v = x[i];
        m = fmaxf(m, fmaxf(fmaxf(fabsf(v.x), fabsf(v.y)), fmaxf(fabsf(v.z), fabsf(v.w))));
    }
    #pragma unroll
    for (int o = 16; o; o >>= 1) m = fmaxf(m, __shfl_xor_sync(0xffffffffu, m, o));
    __shared__ float sm[32];
    int lane = threadIdx.x & 31, wid = threadIdx.x >> 5;
    if (lane == 0) sm[wid] = m;
    __syncthreads();
    if (wid == 0) {
        m = (lane < (int)(blockDim.x >> 5)) ? sm[lane] : 0.f;
        #pragma unroll
        for (int o = 16; o; o >>= 1) m = fmaxf(m, __shfl_xor_sync(0xffffffffu, m, o));
        if (lane == 0) atomicMax(&g_amax_bits, __float_as_uint(m));
    }
}

__device__ __forceinline__ unsigned fp8_of(float v) {
    return (unsigned)__nv_cvt_float_to_fp8(v, __NV_SATFINITE, __NV_E4M3);
}

// One thread -> one 16B chunk (16 floats in, 16 fp8 bytes out, swizzled+tiled).
__global__ void quant_x_kernel(const float4* __restrict__ x, long nchunks) {
    float amax = __uint_as_float(g_amax_bits);
    float inv = 448.f / fmaxf(amax, 1e-12f);
    long i = (long)blockIdx.x * blockDim.x + threadIdx.x;
    long stride = (long)gridDim.x * blockDim.x;
    for (; i < nchunks; i += stride) {
        long m = i >> 8;                  // K/16 = 256 chunks per row
        int ci = (int)(i & 255);
        int kt = ci >> 2, c = ci & 3;
        const float4* src = x + m * (KTOT / 4) + (size_t)ci * 4;
        float4 v0 = src[0], v1 = src[1], v2 = src[2], v3 = src[3];
        uint4 o;
        o.x = fp8_of(v0.x * inv) | (fp8_of(v0.y * inv) << 8) |
              (fp8_of(v0.z * inv) << 16) | (fp8_of(v0.w * inv) << 24);
        o.y = fp8_of(v1.x * inv) | (fp8_of(v1.y * inv) << 8) |
              (fp8_of(v1.z * inv) << 16) | (fp8_of(v1.w * inv) << 24);
        o.z = fp8_of(v2.x * inv) | (fp8_of(v2.y * inv) << 8) |
              (fp8_of(v2.z * inv) << 16) | (fp8_of(v2.w * inv) << 24);
        o.w = fp8_of(v3.x * inv) | (fp8_of(v3.y * inv) << 8) |
              (fp8_of(v3.z * inv) << 16) | (fp8_of(v3.w * inv) << 24);
        int r = (int)(m & (BM - 1));
        size_t tbase = ((size_t)(m >> 7) * KTILES + kt) * TILE_BYTES;
        unsigned off = (unsigned)(r * 64 + ((c ^ ((r >> 1) & 3)) * 16));
        *(uint4*)(g_xq + tbase + off) = o;
    }
}

__global__ void quant_w_kernel(const float4* __restrict__ w, long nchunks) {
    long i = (long)blockIdx.x * blockDim.x + threadIdx.x;
    long stride = (long)gridDim.x * blockDim.x;
    for (; i < nchunks; i += stride) {
        long n = i >> 8;
        int ci = (int)(i & 255);
        int kt = ci >> 2, c = ci & 3;
        const float4* src = w + n * (KTOT / 4) + (size_t)ci * 4;
        float4 v0 = src[0], v1 = src[1], v2 = src[2], v3 = src[3];
        uint4 o;
        o.x = fp8_of(v0.x) | (fp8_of(v0.y) << 8) | (fp8_of(v0.z) << 16) | (fp8_of(v0.w) << 24);
        o.y = fp8_of(v1.x) | (fp8_of(v1.y) << 8) | (fp8_of(v1.z) << 16) | (fp8_of(v1.w) << 24);
        o.z = fp8_of(v2.x) | (fp8_of(v2.y) << 8) | (fp8_of(v2.z) << 16) | (fp8_of(v2.w) << 24);
        o.w = fp8_of(v3.x) | (fp8_of(v3.y) << 8) | (fp8_of(v3.z) << 16) | (fp8_of(v3.w) << 24);
        int r = (int)(n & (BN - 1));
        size_t tbase = ((size_t)(n >> 7) * KTILES + kt) * TILE_BYTES;
        unsigned off = (unsigned)(r * 64 + ((c ^ ((r >> 1) & 3)) * 16));
        *(uint4*)(g_wq + tbase + off) = o;
    }
}

// ============ FP8 mma.sync GEMM: out[M,N] = s*(Xq @ Wq^T) + bias ============
// CTA 128x128x64, 4-stage cp.async.bulk pipeline (tiles are contiguous in
// gmem), 8 warps (4 m-groups x 2 n-groups), warp tile m32 x n64.

__shared__ __align__(8) unsigned long long mb_full[NST];
__shared__ __align__(8) unsigned long long mb_empty[NST];
extern __shared__ __align__(128) unsigned char smem[];

__device__ __forceinline__ void mbar_wait(unsigned mbar, int parity) {
    asm volatile(
        "{\n\t.reg .pred P;\n\t"
        "WL_%=:\n\t"
        "mbarrier.try_wait.parity.acquire.cta.shared::cta.b64 P, [%0], %1, 0x989680;\n\t"
        "@P bra.uni WD_%=;\n\t"
        "bra.uni WL_%=;\n\t"
        "WD_%=:\n\t}"
        :: "r"(mbar), "r"(parity) : "memory");
}

__device__ __forceinline__ void bulk_g2s(unsigned dst, const void* src,
                                         unsigned bytes, unsigned mbar) {
    asm volatile(
        "cp.async.bulk.shared::cluster.global.mbarrier::complete_tx::bytes "
        "[%0], [%1], %2, [%3];"
        :: "r"(dst), "l"(src), "r"(bytes), "r"(mbar) : "memory");
}

__device__ __forceinline__ void mma_e4m3(float* d, const unsigned* a, const unsigned* b) {
    asm volatile(
        "mma.sync.aligned.m16n8k32.row.col.f32.e4m3.e4m3.f32 "
        "{%0,%1,%2,%3}, {%4,%5,%6,%7}, {%8,%9}, {%0,%1,%2,%3};"
        : "+f"(d[0]), "+f"(d[1]), "+f"(d[2]), "+f"(d[3])
        : "r"(a[0]), "r"(a[1]), "r"(a[2]), "r"(a[3]), "r"(b[0]), "r"(b[1]));
}

__device__ __forceinline__ unsigned swz_off(int r, int chunk) {
    return (unsigned)(r * 64 + ((chunk ^ ((r >> 1) & 3)) * 16));
}

__global__ void __launch_bounds__(256, 2)
gemm_fp8(const float* __restrict__ bias, const float* __restrict__ wscale_p,
         float* __restrict__ out, int M, int N, int K) {
    const int tid = threadIdx.x;
    const int wid = tid >> 5;
    const int lane = tid & 31;
    const int wm = wid & 3;          // m-group: 32 rows
    const int wn = wid >> 2;         // n-group: 64 cols
    const int qr = lane >> 2;        // 0..7
    const int qc = lane & 3;         // 0..3

    const unsigned sbase = (unsigned)__cvta_generic_to_shared(smem);
    const unsigned fullb  = (unsigned)__cvta_generic_to_shared(mb_full);
    const unsigned emptyb = (unsigned)__cvta_generic_to_shared(mb_empty);

    if (tid == 0) {
        #pragma unroll
        for (int s = 0; s < NST; s++) {
            asm volatile("mbarrier.init.shared.b64 [%0], 1;"   :: "r"(fullb + s * 8) : "memory");
            asm volatile("mbarrier.init.shared.b64 [%0], 256;" :: "r"(emptyb + s * 8) : "memory");
        }
    }
    __syncthreads();

    const unsigned char* Atiles = g_xq + (size_t)blockIdx.y * KTILES * TILE_BYTES;
    const unsigned char* Btiles = g_wq + (size_t)blockIdx.x * KTILES * TILE_BYTES;

    auto issue_load = [&](int kt) {
        int s = kt & (NST - 1);
        unsigned fb = fullb + s * 8;
        asm volatile("mbarrier.arrive.expect_tx.shared.b64 _, [%0], %1;"
                     :: "r"(fb), "r"((unsigned)STG_BYTES) : "memory");
        unsigned dst = sbase + s * STG_BYTES;
        bulk_g2s(dst, Atiles + (size_t)kt * TILE_BYTES, TILE_BYTES, fb);
        bulk_g2s(dst + TILE_BYTES, Btiles + (size_t)kt * TILE_BYTES, TILE_BYTES, fb);
    };

    if (tid == 0) {
        #pragma unroll
        for (int s = 0; s < NST - 1; s++) issue_load(s);
    }

    float acc[2][8][4];
    #pragma unroll
    for (int mt = 0; mt < 2; mt++)
        #pragma unroll
        for (int j = 0; j < 8; j++)
            #pragma unroll
            for (int q = 0; q < 4; q++) acc[mt][j][q] = 0.f;

    for (int kt = 0; kt < KTILES; kt++) {
        int s = kt & (NST - 1);
        if (tid == 0) {
            int ldkt = kt + NST - 1;
            if (ldkt < KTILES) {
                if (ldkt >= NST)
                    mbar_wait(emptyb + (ldkt & (NST - 1)) * 8, ((ldkt / NST) - 1) & 1);
                issue_load(ldkt);
            }
        }
        mbar_wait(fullb + s * 8, (kt / NST) & 1);

        const unsigned char* As = smem + s * STG_BYTES;
        const unsigned char* Bs = As + TILE_BYTES;

        #pragma unroll
        for (int ks = 0; ks < 2; ks++) {
            unsigned a[2][4];
            #pragma unroll
            for (int mt = 0; mt < 2; mt++) {
                int r0 = wm * 32 + mt * 16 + qr;
                a[mt][0] = *(const unsigned*)(As + swz_off(r0,     ks * 2)     + qc * 4);
                a[mt][1] = *(const unsigned*)(As + swz_off(r0 + 8, ks * 2)     + qc * 4);
                a[mt][2] = *(const unsigned*)(As + swz_off(r0,     ks * 2 + 1) + qc * 4);
                a[mt][3] = *(const unsigned*)(As + swz_off(r0 + 8, ks * 2 + 1) + qc * 4);
            }
            unsigned b[8][2];
            #pragma unroll
            for (int j = 0; j < 8; j++) {
                int rn = wn * 64 + j * 8 + qr;
                b[j][0] = *(const unsigned*)(Bs + swz_off(rn, ks * 2)     + qc * 4);
                b[j][1] = *(const unsigned*)(Bs + swz_off(rn, ks * 2 + 1) + qc * 4);
            }
            #pragma unroll
            for (int mt = 0; mt < 2; mt++)
                #pragma unroll
                for (int j = 0; j < 8; j++)
                    mma_e4m3(acc[mt][j], a[mt], b[j]);
        }
        asm volatile("mbarrier.arrive.shared.b64 _, [%0];"
                     :: "r"(emptyb + s * 8) : "memory");
    }

    // Epilogue: out = acc * (sa*sw) + bias
    float sw = *wscale_p;
    float amax = __uint_as_float(g_amax_bits);
    float sc = (fmaxf(amax, 1e-12f) / 448.f) * sw;

    const int bm = blockIdx.y * BM;
    const int bn = blockIdx.x * BN;
    #pragma unroll
    for (int mt = 0; mt < 2; mt++) {
        int m0 = bm + wm * 32 + mt * 16 + qr;
        #pragma unroll
        for (int j = 0; j < 8; j++) {
            int gn = bn + wn * 64 + j * 8 + 2 * qc;
            float2 bb = *(const float2*)(bias + gn);
            float2 v0, v1;
            v0.x = acc[mt][j][0] * sc + bb.x;
            v0.y = acc[mt][j][1] * sc + bb.y;
            v1.x = acc[mt][j][2] * sc + bb.x;
            v1.y = acc[mt][j][3] * sc + bb.y;
            *(float2*)(out + (size_t)m0 * N + gn) = v0;
            *(float2*)(out + (size_t)(m0 + 8) * N + gn) = v1;
        }
    }
}

extern "C" void kernel_launch(void* const* d_in, const int* in_sizes, int n_in,
                              void* d_out, int out_size) {
    const float* x      = (const float*)d_in[0];
    const float* qw     = (const float*)d_in[1];
    const float* wscale = (const float*)d_in[2];
    const float* bias   = (const float*)d_in[3];
    float* out = (float*)d_out;

    const long xn = in_sizes[0];           // M*K
    const long wn = in_sizes[1];           // N*K
    const int  N  = in_sizes[3];           // D_OUT
    const int  K  = (int)(wn / N);
    const int  M  = (int)(xn / K);

    reset_kernel<<<1, 1>>>();
    amax_kernel<<<2048, 256>>>((const float4*)x, xn / 4);
    quant_x_kernel<<<2048, 256>>>((const float4*)x, xn / 16);
    quant_w_kernel<<<2048, 256>>>((const float4*)qw, wn / 16);

    cudaFuncSetAttribute(gemm_fp8, cudaFuncAttributeMaxDynamicSharedMemorySize, SMEM_DYN);
    dim3 grid(N / BN, M / BM);
    gemm_fp8<<<grid, 256, SMEM_DYN>>>(bias, wscale, out, M, N, K);
}

// round 7
// speedup vs baseline: 1.3214x; 1.0306x over previous
#include <cuda_runtime.h>
#include <cuda_bf16.h>
#include <cuda_fp8.h>

// Problem shape: M=8192 (B*S), N=4096, K=4096
#define M_MAX 8192
#define NTOT  4096
#define KTOT  4096

#define BM 128
#define BN 128
#define BK 64
#define NST 4
#define TILE_BYTES 8192                  // 128 rows x 64 B
#define STG_BYTES (2 * TILE_BYTES)       // A + B per stage
#define SMEM_DYN (NST * STG_BYTES)       // 64 KB
#define KTILES (KTOT / BK)               // 64

// fp8 scratch, tiled: tile t = (rowtile * KTILES + ktile), 8 KB contiguous.
// Within a tile: row r (64B), 16B chunk c stored at r*64 + (c ^ ((r>>1)&3))*16.
__device__ __align__(128) unsigned char g_xq[(size_t)M_MAX * KTOT];  // 32 MB
__device__ __align__(128) unsigned char g_wq[(size_t)NTOT * KTOT];   // 16 MB
__device__ unsigned int g_amax_bits;

__global__ void reset_kernel() { g_amax_bits = 0u; }

__device__ __forceinline__ unsigned fp8_of(float v) {
    return (unsigned)__nv_cvt_float_to_fp8(v, __NV_SATFINITE, __NV_E4M3);
}

// Fused: blocks [0,2048) -> amax(x); blocks [2048,4096) -> quantize W (independent).
__global__ void amax_quantw_kernel(const float4* __restrict__ x, long n4,
                                   const float4* __restrict__ w, long nchw) {
    if (blockIdx.x < 2048) {
        float m = 0.f;
        long i = (long)blockIdx.x * blockDim.x + threadIdx.x;
        long stride = 2048L * blockDim.x;
        for (; i < n4; i += stride) {
            float4 v = x[i];
            m = fmaxf(m, fmaxf(fmaxf(fabsf(v.x), fabsf(v.y)), fmaxf(fabsf(v.z), fabsf(v.w))));
        }
        #pragma unroll
        for (int o = 16; o; o >>= 1) m = fmaxf(m, __shfl_xor_sync(0xffffffffu, m, o));
        __shared__ float sm[32];
        int lane = threadIdx.x & 31, wid = threadIdx.x >> 5;
        if (lane == 0) sm[wid] = m;
        __syncthreads();
        if (wid == 0) {
            m = (lane < (int)(blockDim.x >> 5)) ? sm[lane] : 0.f;
            #pragma unroll
            for (int o = 16; o; o >>= 1) m = fmaxf(m, __shfl_xor_sync(0xffffffffu, m, o));
            if (lane == 0) atomicMax(&g_amax_bits, __float_as_uint(m));
        }
    } else {
        long i = (long)(blockIdx.x - 2048) * blockDim.x + threadIdx.x;
        long stride = 2048L * blockDim.x;
        for (; i < nchw; i += stride) {
            long n = i >> 8;
            int ci = (int)(i & 255);
            int kt = ci >> 2, c = ci & 3;
            const float4* src = w + n * (KTOT / 4) + (size_t)ci * 4;
            float4 v0 = src[0], v1 = src[1], v2 = src[2], v3 = src[3];
            uint4 o;
            o.x = fp8_of(v0.x) | (fp8_of(v0.y) << 8) | (fp8_of(v0.z) << 16) | (fp8_of(v0.w) << 24);
            o.y = fp8_of(v1.x) | (fp8_of(v1.y) << 8) | (fp8_of(v1.z) << 16) | (fp8_of(v1.w) << 24);
            o.z = fp8_of(v2.x) | (fp8_of(v2.y) << 8) | (fp8_of(v2.z) << 16) | (fp8_of(v2.w) << 24);
            o.w = fp8_of(v3.x) | (fp8_of(v3.y) << 8) | (fp8_of(v3.z) << 16) | (fp8_of(v3.w) << 24);
            int r = (int)(n & (BN - 1));
            size_t tbase = ((size_t)(n >> 7) * KTILES + kt) * TILE_BYTES;
            unsigned off = (unsigned)(r * 64 + ((c ^ ((r >> 1) & 3)) * 16));
            *(uint4*)(g_wq + tbase + off) = o;
        }
    }
}

__global__ void quant_x_kernel(const float4* __restrict__ x, long nchunks) {
    float amax = __uint_as_float(g_amax_bits);
    float inv = 448.f / fmaxf(amax, 1e-12f);
    long i = (long)blockIdx.x * blockDim.x + threadIdx.x;
    long stride = (long)gridDim.x * blockDim.x;
    for (; i < nchunks; i += stride) {
        long m = i >> 8;
        int ci = (int)(i & 255);
        int kt = ci >> 2, c = ci & 3;
        const float4* src = x + m * (KTOT / 4) + (size_t)ci * 4;
        float4 v0 = src[0], v1 = src[1], v2 = src[2], v3 = src[3];
        uint4 o;
        o.x = fp8_of(v0.x * inv) | (fp8_of(v0.y * inv) << 8) |
              (fp8_of(v0.z * inv) << 16) | (fp8_of(v0.w * inv) << 24);
        o.y = fp8_of(v1.x * inv) | (fp8_of(v1.y * inv) << 8) |
              (fp8_of(v1.z * inv) << 16) | (fp8_of(v1.w * inv) << 24);
        o.z = fp8_of(v2.x * inv) | (fp8_of(v2.y * inv) << 8) |
              (fp8_of(v2.z * inv) << 16) | (fp8_of(v2.w * inv) << 24);
        o.w = fp8_of(v3.x * inv) | (fp8_of(v3.y * inv) << 8) |
              (fp8_of(v3.z * inv) << 16) | (fp8_of(v3.w * inv) << 24);
        int r = (int)(m & (BM - 1));
        size_t tbase = ((size_t)(m >> 7) * KTILES + kt) * TILE_BYTES;
        unsigned off = (unsigned)(r * 64 + ((c ^ ((r >> 1) & 3)) * 16));
        *(uint4*)(g_xq + tbase + off) = o;
    }
}

// ============ FP8 mma.sync GEMM: out[M,N] = s*(Xq @ Wq^T) + bias ============
// CTA 128x128x64, 4-stage cp.async.bulk pipeline, 8 warps (4m x 2n),
// warp tile m32 x n64, fragments via ldmatrix.x4.

__shared__ __align__(8) unsigned long long mb_full[NST];
__shared__ __align__(8) unsigned long long mb_empty[NST];
extern __shared__ __align__(128) unsigned char smem[];

__device__ __forceinline__ void mbar_wait(unsigned mbar, int parity) {
    asm volatile(
        "{\n\t.reg .pred P;\n\t"
        "WL_%=:\n\t"
        "mbarrier.try_wait.parity.acquire.cta.shared::cta.b64 P, [%0], %1, 0x989680;\n\t"
        "@P bra.uni WD_%=;\n\t"
        "bra.uni WL_%=;\n\t"
        "WD_%=:\n\t}"
        :: "r"(mbar), "r"(parity) : "memory");
}

__device__ __forceinline__ void bulk_g2s(unsigned dst, const void* src,
                                         unsigned bytes, unsigned mbar) {
    asm volatile(
        "cp.async.bulk.shared::cluster.global.mbarrier::complete_tx::bytes "
        "[%0], [%1], %2, [%3];"
        :: "r"(dst), "l"(src), "r"(bytes), "r"(mbar) : "memory");
}

__device__ __forceinline__ void mma_e4m3(float* d, const unsigned* a, const unsigned* b) {
    asm volatile(
        "mma.sync.aligned.m16n8k32.row.col.f32.e4m3.e4m3.f32 "
        "{%0,%1,%2,%3}, {%4,%5,%6,%7}, {%8,%9}, {%0,%1,%2,%3};"
        : "+f"(d[0]), "+f"(d[1]), "+f"(d[2]), "+f"(d[3])
        : "r"(a[0]), "r"(a[1]), "r"(a[2]), "r"(a[3]), "r"(b[0]), "r"(b[1]));
}

__device__ __forceinline__ void ldsm_x4(unsigned* r, unsigned addr) {
    asm volatile(
        "ldmatrix.sync.aligned.m8n8.x4.shared.b16 {%0,%1,%2,%3}, [%4];"
        : "=r"(r[0]), "=r"(r[1]), "=r"(r[2]), "=r"(r[3]) : "r"(addr));
}

__device__ __forceinline__ unsigned swz(int r, int chunk) {
    return (unsigned)(r * 64 + ((chunk ^ ((r >> 1) & 3)) * 16));
}

__global__ void __launch_bounds__(256, 2)
gemm_fp8(const float* __restrict__ bias, const float* __restrict__ wscale_p,
         float* __restrict__ out, int M, int N, int K) {
    const int tid = threadIdx.x;
    const int wid = tid >> 5;
    const int lane = tid & 31;
    const int wm = wid & 3;          // m-group: 32 rows
    const int wn = wid >> 2;         // n-group: 64 cols
    const int qr = lane >> 2;        // 0..7
    const int qc = lane & 3;         // 0..3
    const int g  = lane >> 3;        // ldmatrix lane group 0..3
    const int gi = lane & 7;         // row within matrix

    const unsigned sbase  = (unsigned)__cvta_generic_to_shared(smem);
    const unsigned fullb  = (unsigned)__cvta_generic_to_shared(mb_full);
    const unsigned emptyb = (unsigned)__cvta_generic_to_shared(mb_empty);

    if (tid == 0) {
        #pragma unroll
        for (int s = 0; s < NST; s++) {
            asm volatile("mbarrier.init.shared.b64 [%0], 1;" :: "r"(fullb + s * 8) : "memory");
            asm volatile("mbarrier.init.shared.b64 [%0], 8;" :: "r"(emptyb + s * 8) : "memory");
        }
    }
    __syncthreads();

    // Precomputed ldmatrix addresses (relative to A/B tile base in smem).
    // A (per mt, per ks): matrices {(r,c0),(r+8,c0),(r,c1),(r+8,c1)},
    //   this lane's row = wm*32 + mt*16 + (g&1)*8 + gi, chunk = ks*2 + (g>>1).
    unsigned aoff[2][2];
    #pragma unroll
    for (int mt = 0; mt < 2; mt++) {
        int row = wm * 32 + mt * 16 + (g & 1) * 8 + gi;
        #pragma unroll
        for (int ks = 0; ks < 2; ks++)
            aoff[mt][ks] = sbase + swz(row, ks * 2 + (g >> 1));
    }
    // B (per j-pair p, per ks): matrices {(n,c0),(n,c1),(n+8,c0),(n+8,c1)},
    //   this lane's row = wn*64 + p*16 + (g>>1)*8 + gi, chunk = ks*2 + (g&1).
    unsigned boff[4][2];
    #pragma unroll
    for (int p = 0; p < 4; p++) {
        int row = wn * 64 + p * 16 + (g >> 1) * 8 + gi;
        #pragma unroll
        for (int ks = 0; ks < 2; ks++)
            boff[p][ks] = sbase + TILE_BYTES + swz(row, ks * 2 + (g & 1));
    }

    const unsigned char* Atiles = g_xq + (size_t)blockIdx.y * KTILES * TILE_BYTES;
    const unsigned char* Btiles = g_wq + (size_t)blockIdx.x * KTILES * TILE_BYTES;

    auto issue_load = [&](int kt) {
        int s = kt & (NST - 1);
        unsigned fb = fullb + s * 8;
        asm volatile("mbarrier.arrive.expect_tx.shared.b64 _, [%0], %1;"
                     :: "r"(fb), "r"((unsigned)STG_BYTES) : "memory");
        unsigned dst = sbase + s * STG_BYTES;
        bulk_g2s(dst, Atiles + (size_t)kt * TILE_BYTES, TILE_BYTES, fb);
        bulk_g2s(dst + TILE_BYTES, Btiles + (size_t)kt * TILE_BYTES, TILE_BYTES, fb);
    };

    if (tid == 0) {
        #pragma unroll
        for (int s = 0; s < NST - 1; s++) issue_load(s);
    }

    float acc[2][8][4];
    #pragma unroll
    for (int mt = 0; mt < 2; mt++)
        #pragma unroll
        for (int j = 0; j < 8; j++)
            #pragma unroll
            for (int q = 0; q < 4; q++) acc[mt][j][q] = 0.f;

    for (int kt = 0; kt < KTILES; kt++) {
        int s = kt & (NST - 1);
        if (tid == 0) {
            int ldkt = kt + NST - 1;
            if (ldkt < KTILES) {
                if (ldkt >= NST)
                    mbar_wait(emptyb + (ldkt & (NST - 1)) * 8, ((ldkt / NST) - 1) & 1);
                issue_load(ldkt);
            }
        }
        mbar_wait(fullb + s * 8, (kt / NST) & 1);

        const unsigned so = (unsigned)(s * STG_BYTES);
        #pragma unroll
        for (int ks = 0; ks < 2; ks++) {
            unsigned a[2][4], b[4][4];
            #pragma unroll
            for (int mt = 0; mt < 2; mt++) ldsm_x4(a[mt], aoff[mt][ks] + so);
            #pragma unroll
            for (int p = 0; p < 4; p++) ldsm_x4(b[p], boff[p][ks] + so);
            #pragma unroll
            for (int mt = 0; mt < 2; mt++)
                #pragma unroll
                for (int p = 0; p < 4; p++) {
                    mma_e4m3(acc[mt][2 * p + 0], a[mt], &b[p][0]);
                    mma_e4m3(acc[mt][2 * p + 1], a[mt], &b[p][2]);
                }
        }
        if (lane == 0)
            asm volatile("mbarrier.arrive.shared.b64 _, [%0];"
                         :: "r"(emptyb + s * 8) : "memory");
    }

    // Epilogue: out = acc * (sa*sw) + bias
    float sw = *wscale_p;
    float amax = __uint_as_float(g_amax_bits);
    float sc = (fmaxf(amax, 1e-12f) / 448.f) * sw;

    const int bm = blockIdx.y * BM;
    const int bn = blockIdx.x * BN;
    #pragma unroll
    for (int mt = 0; mt < 2; mt++) {
        int m0 = bm + wm * 32 + mt * 16 + qr;
        #pragma unroll
        for (int j = 0; j < 8; j++) {
            int gn = bn + wn * 64 + j * 8 + 2 * qc;
            float2 bb = *(const float2*)(bias + gn);
            float2 v0, v1;
            v0.x = acc[mt][j][0] * sc + bb.x;
            v0.y = acc[mt][j][1] * sc + bb.y;
            v1.x = acc[mt][j][2] * sc + bb.x;
            v1.y = acc[mt][j][3] * sc + bb.y;
            *(float2*)(out + (size_t)m0 * N + gn) = v0;
            *(float2*)(out + (size_t)(m0 + 8) * N + gn) = v1;
        }
    }
}

extern "C" void kernel_launch(void* const* d_in, const int* in_sizes, int n_in,
                              void* d_out, int out_size) {
    const float* x      = (const float*)d_in[0];
    const float* qw     = (const float*)d_in[1];
    const float* wscale = (const float*)d_in[2];
    const float* bias   = (const float*)d_in[3];
    float* out = (float*)d_out;

    const long xn = in_sizes[0];           // M*K
    const long wn = in_sizes[1];           // N*K
    const int  N  = in_sizes[3];           // D_OUT
    const int  K  = (int)(wn / N);
    const int  M  = (int)(xn / K);

    reset_kernel<<<1, 1>>>();
    amax_quantw_kernel<<<4096, 256>>>((const float4*)x, xn / 4,
                                      (const float4*)qw, wn / 16);
    quant_x_kernel<<<2048, 256>>>((const float4*)x, xn / 16);

    cudaFuncSetAttribute(gemm_fp8, cudaFuncAttributeMaxDynamicSharedMemorySize, SMEM_DYN);
    dim3 grid(N / BN, M / BM);
    gemm_fp8<<<grid, 256, SMEM_DYN>>>(bias, wscale, out, M, N, K);
}

// round 12
// speedup vs baseline: 1.4681x; 1.1111x over previous
#include <cuda_runtime.h>
#include <cuda_bf16.h>
#include <cuda_fp8.h>

// Problem shape: M=8192 (B*S), N=4096, K=4096
#define M_MAX 8192
#define NTOT  4096
#define KTOT  4096

#define BM 128
#define BN 128
#define BK 128
#define NST 3
#define TILE_BYTES 16384                 // 128 rows x 128 B
#define STG_BYTES (2 * TILE_BYTES)       // A + B per stage = 32 KB
#define SMEM_DYN (NST * STG_BYTES)       // 96 KB
#define KTILES (KTOT / BK)               // 32

// fp8 scratch, tiled: tile t = (rowtile * KTILES + ktile), 16 KB contiguous.
// Within a tile: row r (128B), 16B chunk c (0..7) at r*128 + ((c ^ (r&7))*16).
__device__ __align__(128) unsigned char g_xq[(size_t)M_MAX * KTOT];  // 32 MB
__device__ __align__(128) unsigned char g_wq[(size_t)NTOT * KTOT];   // 16 MB
__device__ unsigned int g_amax_bits;

__global__ void reset_kernel() { g_amax_bits = 0u; }

__device__ __forceinline__ unsigned fp8_of(float v) {
    return (unsigned)__nv_cvt_float_to_fp8(v, __NV_SATFINITE, __NV_E4M3);
}

// Fused: blocks [0,2048) -> amax(x); blocks [2048,4096) -> quantize W.
__global__ void amax_quantw_kernel(const float4* __restrict__ x, long n4,
                                   const float4* __restrict__ w, long nchw) {
    if (blockIdx.x < 2048) {
        float m = 0.f;
        long i = (long)blockIdx.x * blockDim.x + threadIdx.x;
        long stride = 2048L * blockDim.x;
        for (; i < n4; i += stride) {
            float4 v = x[i];
            m = fmaxf(m, fmaxf(fmaxf(fabsf(v.x), fabsf(v.y)), fmaxf(fabsf(v.z), fabsf(v.w))));
        }
        #pragma unroll
        for (int o = 16; o; o >>= 1) m = fmaxf(m, __shfl_xor_sync(0xffffffffu, m, o));
        __shared__ float sm[32];
        int lane = threadIdx.x & 31, wid = threadIdx.x >> 5;
        if (lane == 0) sm[wid] = m;
        __syncthreads();
        if (wid == 0) {
            m = (lane < (int)(blockDim.x >> 5)) ? sm[lane] : 0.f;
            #pragma unroll
            for (int o = 16; o; o >>= 1) m = fmaxf(m, __shfl_xor_sync(0xffffffffu, m, o));
            if (lane == 0) atomicMax(&g_amax_bits, __float_as_uint(m));
        }
    } else {
        long i = (long)(blockIdx.x - 2048) * blockDim.x + threadIdx.x;
        long stride = 2048L * blockDim.x;
        for (; i < nchw; i += stride) {
            long n = i >> 8;
            int ci = (int)(i & 255);
            int kt = ci >> 3, c = ci & 7;
            const float4* src = w + n * (KTOT / 4) + (size_t)ci * 4;
            float4 v0 = src[0], v1 = src[1], v2 = src[2], v3 = src[3];
            uint4 o;
            o.x = fp8_of(v0.x) | (fp8_of(v0.y) << 8) | (fp8_of(v0.z) << 16) | (fp8_of(v0.w) << 24);
            o.y = fp8_of(v1.x) | (fp8_of(v1.y) << 8) | (fp8_of(v1.z) << 16) | (fp8_of(v1.w) << 24);
            o.z = fp8_of(v2.x) | (fp8_of(v2.y) << 8) | (fp8_of(v2.z) << 16) | (fp8_of(v2.w) << 24);
            o.w = fp8_of(v3.x) | (fp8_of(v3.y) << 8) | (fp8_of(v3.z) << 16) | (fp8_of(v3.w) << 24);
            int r = (int)(n & 127);
            size_t tbase = ((size_t)(n >> 7) * KTILES + kt) * TILE_BYTES;
            unsigned off = (unsigned)(r * 128 + ((c ^ (r & 7)) * 16));
            *(uint4*)(g_wq + tbase + off) = o;
        }
    }
}

__global__ void quant_x_kernel(const float4* __restrict__ x, long nchunks) {
    float amax = __uint_as_float(g_amax_bits);
    float inv = 448.f / fmaxf(amax, 1e-12f);
    long i = (long)blockIdx.x * blockDim.x + threadIdx.x;
    long stride = (long)gridDim.x * blockDim.x;
    for (; i < nchunks; i += stride) {
        long m = i >> 8;
        int ci = (int)(i & 255);
        int kt = ci >> 3, c = ci & 7;
        const float4* src = x + m * (KTOT / 4) + (size_t)ci * 4;
        float4 v0 = src[0], v1 = src[1], v2 = src[2], v3 = src[3];
        uint4 o;
        o.x = fp8_of(v0.x * inv) | (fp8_of(v0.y * inv) << 8) |
              (fp8_of(v0.z * inv) << 16) | (fp8_of(v0.w * inv) << 24);
        o.y = fp8_of(v1.x * inv) | (fp8_of(v1.y * inv) << 8) |
              (fp8_of(v1.z * inv) << 16) | (fp8_of(v1.w * inv) << 24);
        o.z = fp8_of(v2.x * inv) | (fp8_of(v2.y * inv) << 8) |
              (fp8_of(v2.z * inv) << 16) | (fp8_of(v2.w * inv) << 24);
        o.w = fp8_of(v3.x * inv) | (fp8_of(v3.y * inv) << 8) |
              (fp8_of(v3.z * inv) << 16) | (fp8_of(v3.w * inv) << 24);
        int r = (int)(m & 127);
        size_t tbase = ((size_t)(m >> 7) * KTILES + kt) * TILE_BYTES;
        unsigned off = (unsigned)(r * 128 + ((c ^ (r & 7)) * 16));
        *(uint4*)(g_xq + tbase + off) = o;
    }
}

// ============ FP8 mma.sync GEMM: out[M,N] = s*(Xq @ Wq^T) + bias ============
// CTA 128x128x128, 3-stage cp.async.bulk pipeline, 8 warps (4m x 2n),
// warp tile m32 x n64, fragments via ldmatrix.x4.

__shared__ __align__(8) unsigned long long mb_full[NST];
__shared__ __align__(8) unsigned long long mb_empty[NST];
extern __shared__ __align__(128) unsigned char smem[];

__device__ __forceinline__ void mbar_wait(unsigned mbar, int parity) {
    asm volatile(
        "{\n\t.reg .pred P;\n\t"
        "WL_%=:\n\t"
        "mbarrier.try_wait.parity.acquire.cta.shared::cta.b64 P, [%0], %1, 0x989680;\n\t"
        "@P bra.uni WD_%=;\n\t"
        "bra.uni WL_%=;\n\t"
        "WD_%=:\n\t}"
        :: "r"(mbar), "r"(parity) : "memory");
}

__device__ __forceinline__ void bulk_g2s(unsigned dst, const void* src,
                                         unsigned bytes, unsigned mbar) {
    asm volatile(
        "cp.async.bulk.shared::cluster.global.mbarrier::complete_tx::bytes "
        "[%0], [%1], %2, [%3];"
        :: "r"(dst), "l"(src), "r"(bytes), "r"(mbar) : "memory");
}

__device__ __forceinline__ void mma_e4m3(float* d, const unsigned* a, const unsigned* b) {
    asm volatile(
        "mma.sync.aligned.m16n8k32.row.col.f32.e4m3.e4m3.f32 "
        "{%0,%1,%2,%3}, {%4,%5,%6,%7}, {%8,%9}, {%0,%1,%2,%3};"
        : "+f"(d[0]), "+f"(d[1]), "+f"(d[2]), "+f"(d[3])
        : "r"(a[0]), "r"(a[1]), "r"(a[2]), "r"(a[3]), "r"(b[0]), "r"(b[1]));
}

__device__ __forceinline__ void ldsm_x4(unsigned* r, unsigned addr) {
    asm volatile(
        "ldmatrix.sync.aligned.m8n8.x4.shared.b16 {%0,%1,%2,%3}, [%4];"
        : "=r"(r[0]), "=r"(r[1]), "=r"(r[2]), "=r"(r[3]) : "r"(addr));
}

__global__ void __launch_bounds__(256, 2)
gemm_fp8(const float* __restrict__ bias, const float* __restrict__ wscale_p,
         float* __restrict__ out, int M, int N, int K) {
    const int tid = threadIdx.x;
    const int wid = tid >> 5;
    const int lane = tid & 31;
    const int wm = wid & 3;          // m-group: 32 rows
    const int wn = wid >> 2;         // n-group: 64 cols
    const int qr = lane >> 2;        // 0..7
    const int qc = lane & 3;         // 0..3
    const int g  = lane >> 3;        // ldmatrix lane group 0..3
    const int gi = lane & 7;         // row within 8x16B matrix; row&7 == gi

    const unsigned sbase  = (unsigned)__cvta_generic_to_shared(smem);
    const unsigned fullb  = (unsigned)__cvta_generic_to_shared(mb_full);
    const unsigned emptyb = (unsigned)__cvta_generic_to_shared(mb_empty);

    if (tid == 0) {
        #pragma unroll
        for (int s = 0; s < NST; s++) {
            asm volatile("mbarrier.init.shared.b64 [%0], 1;" :: "r"(fullb + s * 8) : "memory");
            asm volatile("mbarrier.init.shared.b64 [%0], 8;" :: "r"(emptyb + s * 8) : "memory");
        }
    }
    __syncthreads();

    // Row-base addresses (swizzle XOR handled per-ks as ((chunk ^ gi) << 4)).
    unsigned abase[2];   // A: this lane's row for mt fragment family
    #pragma unroll
    for (int mt = 0; mt < 2; mt++)
        abase[mt] = sbase + (unsigned)((wm * 32 + mt * 16 + (g & 1) * 8 + gi) * 128);
    unsigned bbase[4];   // B: this lane's row for p fragment family
    #pragma unroll
    for (int p = 0; p < 4; p++)
        bbase[p] = sbase + TILE_BYTES +
                   (unsigned)((wn * 64 + p * 16 + (g >> 1) * 8 + gi) * 128);
    const int aCh = g >> 1;   // A chunk low bit selector
    const int bCh = g & 1;    // B chunk low bit selector

    const unsigned char* Atiles = g_xq + (size_t)blockIdx.y * KTILES * TILE_BYTES;
    const unsigned char* Btiles = g_wq + (size_t)blockIdx.x * KTILES * TILE_BYTES;

    auto issue_load = [&](int kt, int s) {
        unsigned fb = fullb + s * 8;
        asm volatile("mbarrier.arrive.expect_tx.shared.b64 _, [%0], %1;"
                     :: "r"(fb), "r"((unsigned)STG_BYTES) : "memory");
        unsigned dst = sbase + s * STG_BYTES;
        bulk_g2s(dst, Atiles + (size_t)kt * TILE_BYTES, TILE_BYTES, fb);
        bulk_g2s(dst + TILE_BYTES, Btiles + (size_t)kt * TILE_BYTES, TILE_BYTES, fb);
    };

    if (tid == 0) {
        issue_load(0, 0);
        issue_load(1, 1);
    }

    float acc[2][8][4];
    #pragma unroll
    for (int mt = 0; mt < 2; mt++)
        #pragma unroll
        for (int j = 0; j < 8; j++)
            #pragma unroll
            for (int q = 0; q < 4; q++) acc[mt][j][q] = 0.f;

    int s = 0, ph = 0;
    for (int kt = 0; kt < KTILES; kt++) {
        if (tid == 0) {
            int ldkt = kt + NST - 1;
            if (ldkt < KTILES) {
                int ls = ldkt - (ldkt / NST) * NST;
                if (ldkt >= NST)
                    mbar_wait(emptyb + ls * 8, ((ldkt / NST) - 1) & 1);
                issue_load(ldkt, ls);
            }
        }
        mbar_wait(fullb + s * 8, ph);

        const unsigned so = (unsigned)(s * STG_BYTES);
        #pragma unroll
        for (int ks = 0; ks < 4; ks++) {
            unsigned ca = (unsigned)(((ks * 2 + aCh) ^ gi) << 4);
            unsigned cb = (unsigned)(((ks * 2 + bCh) ^ gi) << 4);
            unsigned a[2][4], b[4][4];
            #pragma unroll
            for (int mt = 0; mt < 2; mt++) ldsm_x4(a[mt], abase[mt] + so + ca);
            #pragma unroll
            for (int p = 0; p < 4; p++) ldsm_x4(b[p], bbase[p] + so + cb);
            #pragma unroll
            for (int mt = 0; mt < 2; mt++)
                #pragma unroll
                for (int p = 0; p < 4; p++) {
                    mma_e4m3(acc[mt][2 * p + 0], a[mt], &b[p][0]);
                    mma_e4m3(acc[mt][2 * p + 1], a[mt], &b[p][2]);
                }
        }
        if (lane == 0)
            asm volatile("mbarrier.arrive.shared.b64 _, [%0];"
                         :: "r"(emptyb + s * 8) : "memory");
        if (++s == NST) { s = 0; ph ^= 1; }
    }

    // Epilogue: out = acc * (sa*sw) + bias
    float sw = *wscale_p;
    float amax = __uint_as_float(g_amax_bits);
    float sc = (fmaxf(amax, 1e-12f) / 448.f) * sw;

    const int bm = blockIdx.y * BM;
    const int bn = blockIdx.x * BN;
    #pragma unroll
    for (int mt = 0; mt < 2; mt++) {
        int m0 = bm + wm * 32 + mt * 16 + qr;
        #pragma unroll
        for (int j = 0; j < 8; j++) {
            int gn = bn + wn * 64 + j * 8 + 2 * qc;
            float2 bb = *(const float2*)(bias + gn);
            float2 v0, v1;
            v0.x = acc[mt][j][0] * sc + bb.x;
            v0.y = acc[mt][j][1] * sc + bb.y;
            v1.x = acc[mt][j][2] * sc + bb.x;
            v1.y = acc[mt][j][3] * sc + bb.y;
            *(float2*)(out + (size_t)m0 * N + gn) = v0;
            *(float2*)(out + (size_t)(m0 + 8) * N + gn) = v1;
        }
    }
}

extern "C" void kernel_launch(void* const* d_in, const int* in_sizes, int n_in,
                              void* d_out, int out_size) {
    const float* x      = (const float*)d_in[0];
    const float* qw     = (const float*)d_in[1];
    const float* wscale = (const float*)d_in[2];
    const float* bias   = (const float*)d_in[3];
    float* out = (float*)d_out;

    const long xn = in_sizes[0];           // M*K
    const long wn = in_sizes[1];           // N*K
    const int  N  = in_sizes[3];           // D_OUT
    const int  K  = (int)(wn / N);
    const int  M  = (int)(xn / K);

    reset_kernel<<<1, 1>>>();
    amax_quantw_kernel<<<4096, 256>>>((const float4*)x, xn / 4,
                                      (const float4*)qw, wn / 16);
    quant_x_kernel<<<2048, 256>>>((const float4*)x, xn / 16);

    cudaFuncSetAttribute(gemm_fp8, cudaFuncAttributeMaxDynamicSharedMemorySize, SMEM_DYN);
    dim3 grid(N / BN, M / BM);
    gemm_fp8<<<grid, 256, SMEM_DYN>>>(bias, wscale, out, M, N, K);
}